// round 1
// baseline (speedup 1.0000x reference)
#include <cuda_runtime.h>
#include <math.h>

#define B_    2
#define T_    2048
#define C_    2048
#define H_    16
#define KVH_  4
#define D_    128
#define GROUPS_ (H_/KVH_)
#define EPS_  1.1920929e-07f

// ---------------- scratch (device globals; no cudaMalloc allowed) ----------
__device__ float g_qlin[B_*T_*H_*D_];     // [B*T, H*D]   q = x@Wq^T
__device__ float g_klin[B_*T_*KVH_*D_];   // [B*T, KVH*D]
__device__ float g_vlin[B_*T_*KVH_*D_];   // [B*T, KVH*D]
__device__ float g_qt  [B_*T_*H_*D_];     // [B, H, T, D] rope+rms+scale
__device__ float g_kt  [B_*T_*KVH_*D_];   // [B, KVH, T, D]
__device__ float g_y   [B_*T_*H_*D_];     // [B, T, H*D]  attention output

// ---------------------------------------------------------------------------
// SGEMM:  C[m][n] = sum_k A[m*K+k] * W[n*K+k]   (A row-major [M,K], W [N,K])
// 128x128 tile, BK=16, 256 threads, 8x8 microtile.
// M,N multiples of 128; K multiple of 16. (holds for all our shapes)
// ---------------------------------------------------------------------------
__global__ __launch_bounds__(256) void sgemm_nt(
    const float* __restrict__ A, const float* __restrict__ W,
    float* __restrict__ C, int M, int N, int K)
{
    __shared__ float As[16][132];
    __shared__ float Bs[16][132];

    const int tid = threadIdx.x;
    const int tx = tid & 15;
    const int ty = tid >> 4;
    const int m0 = blockIdx.y * 128;
    const int n0 = blockIdx.x * 128;

    float acc[8][8];
    #pragma unroll
    for (int i = 0; i < 8; i++)
        #pragma unroll
        for (int j = 0; j < 8; j++) acc[i][j] = 0.f;

    for (int k0 = 0; k0 < K; k0 += 16) {
        #pragma unroll
        for (int l = 0; l < 2; l++) {
            int idx4 = tid + l * 256;        // 0..511 : 128 rows x 4 float4
            int mm = idx4 >> 2;
            int k4 = (idx4 & 3) << 2;
            float4 va = *(const float4*)(A + (size_t)(m0 + mm) * K + k0 + k4);
            As[k4 + 0][mm] = va.x; As[k4 + 1][mm] = va.y;
            As[k4 + 2][mm] = va.z; As[k4 + 3][mm] = va.w;
            float4 vb = *(const float4*)(W + (size_t)(n0 + mm) * K + k0 + k4);
            Bs[k4 + 0][mm] = vb.x; Bs[k4 + 1][mm] = vb.y;
            Bs[k4 + 2][mm] = vb.z; Bs[k4 + 3][mm] = vb.w;
        }
        __syncthreads();

        #pragma unroll
        for (int kk = 0; kk < 16; kk++) {
            float a[8], b[8];
            *(float4*)&a[0] = *(const float4*)&As[kk][ty * 8];
            *(float4*)&a[4] = *(const float4*)&As[kk][ty * 8 + 4];
            *(float4*)&b[0] = *(const float4*)&Bs[kk][tx * 8];
            *(float4*)&b[4] = *(const float4*)&Bs[kk][tx * 8 + 4];
            #pragma unroll
            for (int i = 0; i < 8; i++)
                #pragma unroll
                for (int j = 0; j < 8; j++)
                    acc[i][j] = fmaf(a[i], b[j], acc[i][j]);
        }
        __syncthreads();
    }

    #pragma unroll
    for (int i = 0; i < 8; i++) {
        float* crow = C + (size_t)(m0 + ty * 8 + i) * N + n0 + tx * 8;
        *(float4*)(crow)     = make_float4(acc[i][0], acc[i][1], acc[i][2], acc[i][3]);
        *(float4*)(crow + 4) = make_float4(acc[i][4], acc[i][5], acc[i][6], acc[i][7]);
    }
}

// ---------------------------------------------------------------------------
// Fused RoPE + RMSNorm (+ optional softmax scale folded in), with transpose to
// [B, NH, T, D]. One 64-thread block per (b, t, head) row.
// in : [B*T, NH*D]   (blockIdx.x = (b*T + t)*NH + h)
// ---------------------------------------------------------------------------
__global__ __launch_bounds__(64) void rope_rms_kernel(
    const float* __restrict__ in, const float* __restrict__ cosb,
    const float* __restrict__ sinb, float* __restrict__ out,
    int NH, float scale)
{
    const int bid = blockIdx.x;
    const int h  = bid % NH;
    const int bt = bid / NH;
    const int t  = bt % T_;
    const int b  = bt / T_;
    const int i  = threadIdx.x;   // 0..63

    const float* row = in + (size_t)bid * D_;
    float x1 = row[i];
    float x2 = row[i + 64];
    float cv = cosb[t * 64 + i];
    float sv = sinb[t * 64 + i];
    float o1 = x1 * cv + x2 * sv;
    float o2 = x2 * cv - x1 * sv;

    float ss = o1 * o1 + o2 * o2;
    #pragma unroll
    for (int off = 16; off; off >>= 1)
        ss += __shfl_xor_sync(0xffffffffu, ss, off);
    __shared__ float sred[2];
    if ((i & 31) == 0) sred[i >> 5] = ss;
    __syncthreads();
    float tot = sred[0] + sred[1];
    float r = rsqrtf(tot * (1.f / 128.f) + EPS_) * scale;

    float* orow = out + (((size_t)(b * NH + h) * T_ + t) * D_);
    orow[i]      = o1 * r;
    orow[i + 64] = o2 * r;
}

// ---------------------------------------------------------------------------
// Causal flash attention (fp32, online softmax).
// Q: [B,H,T,D] (pre-scaled), K: [B,KVH,T,D], V: [B*T, KVH*D], Y: [B,T,H*D]
// Block: 256 threads, 64 query rows x 64 key cols per tile.
// Thread (ty,tx) in 16x16 grid: 4 score rows x 4 score cols; owns output
// d-range [tx*8, tx*8+8) for its 4 rows.
// ---------------------------------------------------------------------------
#define FA_BM 64
#define FA_BN 64
#define SQ    132     // padded row stride for Q/K/V tiles
#define SP    68      // padded row stride for P tile

__global__ __launch_bounds__(256) void flash_kernel(
    const float* __restrict__ Qt, const float* __restrict__ Kt,
    const float* __restrict__ Vlin, float* __restrict__ Y)
{
    extern __shared__ float sm[];
    float* Qs = sm;               // 64 * 132
    float* Ks = Qs + 64 * SQ;     // 64 * 132
    float* Vs = Ks + 64 * SQ;     // 64 * 132
    float* Ps = Vs + 64 * SQ;     // 64 * 68

    const int tid = threadIdx.x;
    const int tx = tid & 15;
    const int ty = tid >> 4;
    const int qtile = blockIdx.x;
    const int bh = blockIdx.y;            // b*H + h
    const int b  = bh / H_;
    const int h  = bh % H_;
    const int kvh = h / GROUPS_;
    const int q0 = qtile * FA_BM;

    // ---- load Q tile (64 x 128) ----
    {
        const float* qbase = Qt + ((size_t)bh * T_ + q0) * D_;
        #pragma unroll
        for (int l = 0; l < 8; l++) {
            int idx4 = tid + l * 256;        // 0..2047
            int row = idx4 >> 5;
            int c4  = (idx4 & 31) << 2;
            *(float4*)&Qs[row * SQ + c4] =
                *(const float4*)(qbase + (size_t)row * D_ + c4);
        }
    }

    float acc[4][8];
    #pragma unroll
    for (int i = 0; i < 4; i++)
        #pragma unroll
        for (int d = 0; d < 8; d++) acc[i][d] = 0.f;
    float mrow[4], lrow[4];
    #pragma unroll
    for (int i = 0; i < 4; i++) { mrow[i] = -INFINITY; lrow[i] = 0.f; }

    const float* kbase = Kt + ((size_t)(b * KVH_ + kvh) * T_) * D_;

    for (int kt = 0; kt <= qtile; kt++) {
        const int k0 = kt * FA_BN;
        __syncthreads();   // previous tile's PV reads of Vs / Ps done
        // ---- load K, V tiles ----
        #pragma unroll
        for (int l = 0; l < 8; l++) {
            int idx4 = tid + l * 256;
            int row = idx4 >> 5;
            int c4  = (idx4 & 31) << 2;
            *(float4*)&Ks[row * SQ + c4] =
                *(const float4*)(kbase + (size_t)(k0 + row) * D_ + c4);
            *(float4*)&Vs[row * SQ + c4] =
                *(const float4*)(Vlin + (((size_t)(b * T_ + k0 + row)) * KVH_ + kvh) * D_ + c4);
        }
        __syncthreads();

        // ---- scores: s[i][j] = q_i . k_j ----
        float s[4][4];
        #pragma unroll
        for (int i = 0; i < 4; i++)
            #pragma unroll
            for (int j = 0; j < 4; j++) s[i][j] = 0.f;

        #pragma unroll 8
        for (int d0 = 0; d0 < D_; d0 += 4) {
            float4 a0 = *(const float4*)&Qs[(ty * 4 + 0) * SQ + d0];
            float4 a1 = *(const float4*)&Qs[(ty * 4 + 1) * SQ + d0];
            float4 a2 = *(const float4*)&Qs[(ty * 4 + 2) * SQ + d0];
            float4 a3 = *(const float4*)&Qs[(ty * 4 + 3) * SQ + d0];
            float4 b0 = *(const float4*)&Ks[(tx * 4 + 0) * SQ + d0];
            float4 b1 = *(const float4*)&Ks[(tx * 4 + 1) * SQ + d0];
            float4 b2 = *(const float4*)&Ks[(tx * 4 + 2) * SQ + d0];
            float4 b3 = *(const float4*)&Ks[(tx * 4 + 3) * SQ + d0];
            float4 aa[4] = {a0, a1, a2, a3};
            float4 bb[4] = {b0, b1, b2, b3};
            #pragma unroll
            for (int i = 0; i < 4; i++)
                #pragma unroll
                for (int j = 0; j < 4; j++) {
                    s[i][j] = fmaf(aa[i].x, bb[j].x, s[i][j]);
                    s[i][j] = fmaf(aa[i].y, bb[j].y, s[i][j]);
                    s[i][j] = fmaf(aa[i].z, bb[j].z, s[i][j]);
                    s[i][j] = fmaf(aa[i].w, bb[j].w, s[i][j]);
                }
        }

        // ---- causal mask (diagonal tile only) ----
        if (kt == qtile) {
            #pragma unroll
            for (int i = 0; i < 4; i++) {
                int qg = q0 + ty * 4 + i;
                #pragma unroll
                for (int j = 0; j < 4; j++) {
                    int kg = k0 + tx * 4 + j;
                    if (kg > qg) s[i][j] = -1e30f;
                }
            }
        }

        // ---- online softmax (row reductions over the 16-lane tx group) ----
        float p[4][4];
        #pragma unroll
        for (int i = 0; i < 4; i++) {
            float mx = fmaxf(fmaxf(s[i][0], s[i][1]), fmaxf(s[i][2], s[i][3]));
            #pragma unroll
            for (int off = 1; off < 16; off <<= 1)
                mx = fmaxf(mx, __shfl_xor_sync(0xffffffffu, mx, off));
            float mnew = fmaxf(mrow[i], mx);
            float alpha = __expf(mrow[i] - mnew);
            float rs = 0.f;
            #pragma unroll
            for (int j = 0; j < 4; j++) {
                p[i][j] = __expf(s[i][j] - mnew);
                rs += p[i][j];
            }
            #pragma unroll
            for (int off = 1; off < 16; off <<= 1)
                rs += __shfl_xor_sync(0xffffffffu, rs, off);
            lrow[i] = lrow[i] * alpha + rs;
            mrow[i] = mnew;
            #pragma unroll
            for (int d = 0; d < 8; d++) acc[i][d] *= alpha;
        }

        // ---- store P tile (row group is intra-warp: syncwarp suffices) ----
        #pragma unroll
        for (int i = 0; i < 4; i++)
            #pragma unroll
            for (int j = 0; j < 4; j++)
                Ps[(ty * 4 + i) * SP + tx * 4 + j] = p[i][j];
        __syncwarp();

        // ---- PV accumulate: acc[i][0..7] over d-range [tx*8, tx*8+8) ----
        #pragma unroll 4
        for (int j = 0; j < FA_BN; j++) {
            float p0 = Ps[(ty * 4 + 0) * SP + j];
            float p1 = Ps[(ty * 4 + 1) * SP + j];
            float p2 = Ps[(ty * 4 + 2) * SP + j];
            float p3 = Ps[(ty * 4 + 3) * SP + j];
            float4 v0 = *(const float4*)&Vs[j * SQ + tx * 8];
            float4 v1 = *(const float4*)&Vs[j * SQ + tx * 8 + 4];
            acc[0][0] = fmaf(p0, v0.x, acc[0][0]); acc[0][1] = fmaf(p0, v0.y, acc[0][1]);
            acc[0][2] = fmaf(p0, v0.z, acc[0][2]); acc[0][3] = fmaf(p0, v0.w, acc[0][3]);
            acc[0][4] = fmaf(p0, v1.x, acc[0][4]); acc[0][5] = fmaf(p0, v1.y, acc[0][5]);
            acc[0][6] = fmaf(p0, v1.z, acc[0][6]); acc[0][7] = fmaf(p0, v1.w, acc[0][7]);
            acc[1][0] = fmaf(p1, v0.x, acc[1][0]); acc[1][1] = fmaf(p1, v0.y, acc[1][1]);
            acc[1][2] = fmaf(p1, v0.z, acc[1][2]); acc[1][3] = fmaf(p1, v0.w, acc[1][3]);
            acc[1][4] = fmaf(p1, v1.x, acc[1][4]); acc[1][5] = fmaf(p1, v1.y, acc[1][5]);
            acc[1][6] = fmaf(p1, v1.z, acc[1][6]); acc[1][7] = fmaf(p1, v1.w, acc[1][7]);
            acc[2][0] = fmaf(p2, v0.x, acc[2][0]); acc[2][1] = fmaf(p2, v0.y, acc[2][1]);
            acc[2][2] = fmaf(p2, v0.z, acc[2][2]); acc[2][3] = fmaf(p2, v0.w, acc[2][3]);
            acc[2][4] = fmaf(p2, v1.x, acc[2][4]); acc[2][5] = fmaf(p2, v1.y, acc[2][5]);
            acc[2][6] = fmaf(p2, v1.z, acc[2][6]); acc[2][7] = fmaf(p2, v1.w, acc[2][7]);
            acc[3][0] = fmaf(p3, v0.x, acc[3][0]); acc[3][1] = fmaf(p3, v0.y, acc[3][1]);
            acc[3][2] = fmaf(p3, v0.z, acc[3][2]); acc[3][3] = fmaf(p3, v0.w, acc[3][3]);
            acc[3][4] = fmaf(p3, v1.x, acc[3][4]); acc[3][5] = fmaf(p3, v1.y, acc[3][5]);
            acc[3][6] = fmaf(p3, v1.z, acc[3][6]); acc[3][7] = fmaf(p3, v1.w, acc[3][7]);
        }
    }

    // ---- epilogue: Y[b, t, h*D + d] = acc / l ----
    #pragma unroll
    for (int i = 0; i < 4; i++) {
        float il = 1.f / lrow[i];
        int qg = q0 + ty * 4 + i;
        float* yrow = Y + (((size_t)(b * T_ + qg)) * H_ + h) * D_ + tx * 8;
        *(float4*)(yrow)     = make_float4(acc[i][0] * il, acc[i][1] * il,
                                           acc[i][2] * il, acc[i][3] * il);
        *(float4*)(yrow + 4) = make_float4(acc[i][4] * il, acc[i][5] * il,
                                           acc[i][6] * il, acc[i][7] * il);
    }
}

// ---------------------------------------------------------------------------
extern "C" void kernel_launch(void* const* d_in, const int* in_sizes, int n_in,
                              void* d_out, int out_size)
{
    const float* x    = (const float*)d_in[0];
    const float* cosb = (const float*)d_in[1];
    const float* sinb = (const float*)d_in[2];
    const float* Wq   = (const float*)d_in[3];
    const float* Wk   = (const float*)d_in[4];
    const float* Wv   = (const float*)d_in[5];
    const float* Wo   = (const float*)d_in[6];
    float* out = (float*)d_out;

    float *qlin, *klin, *vlin, *qt, *ktp, *y;
    cudaGetSymbolAddress((void**)&qlin, g_qlin);
    cudaGetSymbolAddress((void**)&klin, g_klin);
    cudaGetSymbolAddress((void**)&vlin, g_vlin);
    cudaGetSymbolAddress((void**)&qt,   g_qt);
    cudaGetSymbolAddress((void**)&ktp,  g_kt);
    cudaGetSymbolAddress((void**)&y,    g_y);

    const int M = B_ * T_;  // 4096

    // QKV projections
    sgemm_nt<<<dim3((H_ * D_) / 128, M / 128), 256>>>(x, Wq, qlin, M, H_ * D_, C_);
    sgemm_nt<<<dim3((KVH_ * D_) / 128, M / 128), 256>>>(x, Wk, klin, M, KVH_ * D_, C_);
    sgemm_nt<<<dim3((KVH_ * D_) / 128, M / 128), 256>>>(x, Wv, vlin, M, KVH_ * D_, C_);

    // RoPE + RMSNorm (+ fold softmax scale 1/sqrt(D) into q)
    rope_rms_kernel<<<B_ * T_ * H_, 64>>>(qlin, cosb, sinb, qt, H_,
                                          0.08838834764831845f);
    rope_rms_kernel<<<B_ * T_ * KVH_, 64>>>(klin, cosb, sinb, ktp, KVH_, 1.0f);

    // Flash attention
    size_t smem = (size_t)(3 * 64 * SQ + 64 * SP) * sizeof(float); // 118784 B
    cudaFuncSetAttribute(flash_kernel,
                         cudaFuncAttributeMaxDynamicSharedMemorySize, (int)smem);
    flash_kernel<<<dim3(T_ / FA_BM, B_ * H_), 256, smem>>>(qt, ktp, vlin, y);

    // Output projection
    sgemm_nt<<<dim3(C_ / 128, M / 128), 256>>>(y, Wo, out, M, C_, C_);
}

// round 2
// speedup vs baseline: 3.5988x; 3.5988x over previous
#include <cuda_runtime.h>
#include <math.h>

#define B_    2
#define T_    2048
#define C_    2048
#define H_    16
#define KVH_  4
#define D_    128
#define GROUPS_ (H_/KVH_)
#define EPS_  1.1920929e-07f

// ---------------- scratch (device globals; no cudaMalloc allowed) ----------
__device__ float g_qlin[B_*T_*H_*D_];     // [B*T, H*D]
__device__ float g_klin[B_*T_*KVH_*D_];
__device__ float g_vlin[B_*T_*KVH_*D_];
__device__ float g_qt  [B_*T_*H_*D_];     // [B, H, T, D] rope+rms+scale
__device__ float g_kt  [B_*T_*KVH_*D_];   // [B, KVH, T, D]
__device__ float g_y   [B_*T_*H_*D_];     // [B, T, H*D]

// ---------------------------------------------------------------------------
// tf32 helpers
// ---------------------------------------------------------------------------
__device__ __forceinline__ unsigned f2tf(float f) {
    unsigned u;
    asm("cvt.rna.tf32.f32 %0, %1;" : "=r"(u) : "f"(f));
    return u;
}

__device__ __forceinline__ void mma8(float* d, const unsigned* a, const unsigned* b) {
    asm volatile(
        "mma.sync.aligned.m16n8k8.row.col.f32.tf32.tf32.f32 "
        "{%0,%1,%2,%3}, {%4,%5,%6,%7}, {%8,%9}, {%0,%1,%2,%3};\n"
        : "+f"(d[0]), "+f"(d[1]), "+f"(d[2]), "+f"(d[3])
        : "r"(a[0]), "r"(a[1]), "r"(a[2]), "r"(a[3]), "r"(b[0]), "r"(b[1]));
}

// ---------------------------------------------------------------------------
// tf32 GEMM:  C[m][n] = sum_k A[m][k] * W[n][k]    (A [M,K], W [N,K], row-major)
// Tile 128x128, BK=32, 256 threads = 8 warps in 4(M) x 2(N); warp tile 32x64.
// M,N multiples of 128; K multiple of 32.
// ---------------------------------------------------------------------------
__global__ __launch_bounds__(256) void gemm_tf32(
    const float* __restrict__ A, const float* __restrict__ W,
    float* __restrict__ C, int M, int N, int K)
{
    __shared__ unsigned As[128 * 36];
    __shared__ unsigned Ws[128 * 36];

    const int tid  = threadIdx.x;
    const int lane = tid & 31;
    const int wid  = tid >> 5;
    const int g    = lane >> 2;     // 0..7
    const int t    = lane & 3;      // 0..3
    const int m0 = blockIdx.y * 128;
    const int n0 = blockIdx.x * 128;
    const int wm = (wid & 3) * 32;
    const int wn = (wid >> 2) * 64;

    float acc[2][8][4];
    #pragma unroll
    for (int mi = 0; mi < 2; mi++)
        #pragma unroll
        for (int j = 0; j < 8; j++)
            #pragma unroll
            for (int c = 0; c < 4; c++) acc[mi][j][c] = 0.f;

    for (int k0 = 0; k0 < K; k0 += 32) {
        // stage A[128x32], W[128x32] -> smem as tf32 bits (stride 36)
        #pragma unroll
        for (int l = 0; l < 4; l++) {
            int idx = tid + l * 256;          // 0..1023
            int r  = idx >> 3;
            int c4 = (idx & 7) * 4;
            float4 va = *(const float4*)(A + (size_t)(m0 + r) * K + k0 + c4);
            unsigned* pa = &As[r * 36 + c4];
            pa[0] = f2tf(va.x); pa[1] = f2tf(va.y);
            pa[2] = f2tf(va.z); pa[3] = f2tf(va.w);
            float4 vb = *(const float4*)(W + (size_t)(n0 + r) * K + k0 + c4);
            unsigned* pb = &Ws[r * 36 + c4];
            pb[0] = f2tf(vb.x); pb[1] = f2tf(vb.y);
            pb[2] = f2tf(vb.z); pb[3] = f2tf(vb.w);
        }
        __syncthreads();

        #pragma unroll
        for (int kk = 0; kk < 32; kk += 8) {
            unsigned a[2][4], b[8][2];
            #pragma unroll
            for (int mi = 0; mi < 2; mi++) {
                int r = wm + mi * 16;
                a[mi][0] = As[(r + g)     * 36 + kk + t];
                a[mi][1] = As[(r + g + 8) * 36 + kk + t];
                a[mi][2] = As[(r + g)     * 36 + kk + t + 4];
                a[mi][3] = As[(r + g + 8) * 36 + kk + t + 4];
            }
            #pragma unroll
            for (int j = 0; j < 8; j++) {
                b[j][0] = Ws[(wn + j * 8 + g) * 36 + kk + t];
                b[j][1] = Ws[(wn + j * 8 + g) * 36 + kk + t + 4];
            }
            #pragma unroll
            for (int mi = 0; mi < 2; mi++)
                #pragma unroll
                for (int j = 0; j < 8; j++)
                    mma8(acc[mi][j], a[mi], b[j]);
        }
        __syncthreads();
    }

    #pragma unroll
    for (int mi = 0; mi < 2; mi++) {
        int r0 = m0 + wm + mi * 16 + g;
        #pragma unroll
        for (int j = 0; j < 8; j++) {
            int cc = n0 + wn + j * 8 + 2 * t;
            *(float2*)(C + (size_t)r0 * N + cc) =
                make_float2(acc[mi][j][0], acc[mi][j][1]);
            *(float2*)(C + (size_t)(r0 + 8) * N + cc) =
                make_float2(acc[mi][j][2], acc[mi][j][3]);
        }
    }
}

// ---------------------------------------------------------------------------
// Fused RoPE + RMSNorm (+ optional scale), transpose to [B, NH, T, D].
// ---------------------------------------------------------------------------
__global__ __launch_bounds__(64) void rope_rms_kernel(
    const float* __restrict__ in, const float* __restrict__ cosb,
    const float* __restrict__ sinb, float* __restrict__ out,
    int NH, float scale)
{
    const int bid = blockIdx.x;
    const int h  = bid % NH;
    const int bt = bid / NH;
    const int t  = bt % T_;
    const int b  = bt / T_;
    const int i  = threadIdx.x;   // 0..63

    const float* row = in + (size_t)bid * D_;
    float x1 = row[i];
    float x2 = row[i + 64];
    float cv = cosb[t * 64 + i];
    float sv = sinb[t * 64 + i];
    float o1 = x1 * cv + x2 * sv;
    float o2 = x2 * cv - x1 * sv;

    float ss = o1 * o1 + o2 * o2;
    #pragma unroll
    for (int off = 16; off; off >>= 1)
        ss += __shfl_xor_sync(0xffffffffu, ss, off);
    __shared__ float sred[2];
    if ((i & 31) == 0) sred[i >> 5] = ss;
    __syncthreads();
    float tot = sred[0] + sred[1];
    float r = rsqrtf(tot * (1.f / 128.f) + EPS_) * scale;

    float* orow = out + (((size_t)(b * NH + h) * T_ + t) * D_);
    orow[i]      = o1 * r;
    orow[i + 64] = o2 * r;
}

// ---------------------------------------------------------------------------
// Causal flash attention, tf32 mma, online softmax.
// Q: [B,H,T,D] (pre-scaled), K: [B,KVH,T,D], V: [B*T, KVH*D], Y: [B,T,H*D]
// CTA: 256 threads = 8 warps. 128 query rows per CTA (16 per warp), 64 keys/tile.
// ---------------------------------------------------------------------------
#define FSQ 132     // Qs/Ks row stride (words);  132 % 32 == 4 -> conflict-free frags
#define FSV 136     // Vs row stride;             136 % 32 == 8 -> conflict-free frags
#define FSP 68      // Ps row stride;              68 % 32 == 4

__global__ __launch_bounds__(256) void flash_tf32(
    const float* __restrict__ Qt, const float* __restrict__ Kt,
    const float* __restrict__ Vlin, float* __restrict__ Y)
{
    extern __shared__ unsigned smu[];
    unsigned* Qs = smu;                    // 128 * 132
    unsigned* Ks = Qs + 128 * FSQ;         //  64 * 132
    unsigned* Vs = Ks + 64 * FSQ;          //  64 * 136
    unsigned* Ps = Vs + 64 * FSV;          // 128 * 68

    const int tid  = threadIdx.x;
    const int lane = tid & 31;
    const int wid  = tid >> 5;
    const int g    = lane >> 2;
    const int t    = lane & 3;
    const int qb = blockIdx.x;
    const int q0 = qb * 128;
    const int bh = blockIdx.y;             // b*H + h
    const int b  = bh / H_;
    const int h  = bh % H_;
    const int kvh = h / GROUPS_;
    const int wr  = wid * 16;              // warp's first query row (within tile)

    // ---- stage Q tile (128 x 128) as tf32 ----
    {
        const float* qbase = Qt + ((size_t)bh * T_ + q0) * D_;
        #pragma unroll
        for (int l = 0; l < 16; l++) {
            int idx = tid + l * 256;          // 0..4095
            int r  = idx >> 5;
            int c4 = (idx & 31) * 4;
            float4 v = *(const float4*)(qbase + (size_t)r * D_ + c4);
            unsigned* p = &Qs[r * FSQ + c4];
            p[0] = f2tf(v.x); p[1] = f2tf(v.y); p[2] = f2tf(v.z); p[3] = f2tf(v.w);
        }
    }

    float oacc[16][4];
    #pragma unroll
    for (int j = 0; j < 16; j++)
        #pragma unroll
        for (int c = 0; c < 4; c++) oacc[j][c] = 0.f;
    float mrow[2] = {-INFINITY, -INFINITY};
    float lrow[2] = {0.f, 0.f};

    const float* kbase = Kt + ((size_t)(b * KVH_ + kvh) * T_) * D_;
    const float* vbase = Vlin + ((size_t)b * T_) * (KVH_ * D_) + kvh * D_;

    const int nkt = qb * 2 + 2;
    for (int kt = 0; kt < nkt; kt++) {
        const int k0 = kt * 64;
        __syncthreads();   // prev PV reads of Vs/Ps done; Q stage visible on kt=0
        // ---- stage K, V tiles (64 x 128 each) ----
        #pragma unroll
        for (int l = 0; l < 8; l++) {
            int idx = tid + l * 256;          // 0..2047
            int r  = idx >> 5;
            int c4 = (idx & 31) * 4;
            float4 kv = *(const float4*)(kbase + (size_t)(k0 + r) * D_ + c4);
            unsigned* pk = &Ks[r * FSQ + c4];
            pk[0] = f2tf(kv.x); pk[1] = f2tf(kv.y); pk[2] = f2tf(kv.z); pk[3] = f2tf(kv.w);
            float4 vv = *(const float4*)(vbase + (size_t)(k0 + r) * (KVH_ * D_) + c4);
            unsigned* pv = &Vs[r * FSV + c4];
            pv[0] = f2tf(vv.x); pv[1] = f2tf(vv.y); pv[2] = f2tf(vv.z); pv[3] = f2tf(vv.w);
        }
        __syncthreads();

        // ---- S = Q . K^T  (warp: 16 x 64) ----
        float s[8][4];
        #pragma unroll
        for (int j = 0; j < 8; j++)
            #pragma unroll
            for (int c = 0; c < 4; c++) s[j][c] = 0.f;

        #pragma unroll
        for (int ks = 0; ks < 16; ks++) {
            unsigned qa[4];
            qa[0] = Qs[(wr + g)     * FSQ + ks * 8 + t];
            qa[1] = Qs[(wr + g + 8) * FSQ + ks * 8 + t];
            qa[2] = Qs[(wr + g)     * FSQ + ks * 8 + t + 4];
            qa[3] = Qs[(wr + g + 8) * FSQ + ks * 8 + t + 4];
            #pragma unroll
            for (int j = 0; j < 8; j++) {
                unsigned kb[2];
                kb[0] = Ks[(j * 8 + g) * FSQ + ks * 8 + t];
                kb[1] = Ks[(j * 8 + g) * FSQ + ks * 8 + t + 4];
                mma8(s[j], qa, kb);
            }
        }

        // ---- causal mask (last two tiles only) ----
        if (kt >= nkt - 2) {
            int row0 = q0 + wr + g;
            int row1 = row0 + 8;
            #pragma unroll
            for (int j = 0; j < 8; j++) {
                int c0 = k0 + j * 8 + 2 * t;
                int c1 = c0 + 1;
                if (c0 > row0) s[j][0] = -1e30f;
                if (c1 > row0) s[j][1] = -1e30f;
                if (c0 > row1) s[j][2] = -1e30f;
                if (c1 > row1) s[j][3] = -1e30f;
            }
        }

        // ---- online softmax (rows g and g+8; reduce over 4-lane groups) ----
        #pragma unroll
        for (int ri = 0; ri < 2; ri++) {
            const int i0 = ri * 2, i1 = ri * 2 + 1;
            float mx = -1e30f;
            #pragma unroll
            for (int j = 0; j < 8; j++)
                mx = fmaxf(mx, fmaxf(s[j][i0], s[j][i1]));
            mx = fmaxf(mx, __shfl_xor_sync(0xffffffffu, mx, 1));
            mx = fmaxf(mx, __shfl_xor_sync(0xffffffffu, mx, 2));
            float mnew = fmaxf(mrow[ri], mx);
            float alpha = __expf(mrow[ri] - mnew);
            float rs = 0.f;
            #pragma unroll
            for (int j = 0; j < 8; j++) {
                float p0 = __expf(s[j][i0] - mnew);
                float p1 = __expf(s[j][i1] - mnew);
                s[j][i0] = p0; s[j][i1] = p1;
                rs += p0 + p1;
            }
            rs += __shfl_xor_sync(0xffffffffu, rs, 1);
            rs += __shfl_xor_sync(0xffffffffu, rs, 2);
            lrow[ri] = lrow[ri] * alpha + rs;
            mrow[ri] = mnew;
            #pragma unroll
            for (int j = 0; j < 16; j++) {
                oacc[j][i0] *= alpha;
                oacc[j][i1] *= alpha;
            }
        }

        // ---- write P tile (tf32 bits); rows are warp-private ----
        #pragma unroll
        for (int j = 0; j < 8; j++) {
            Ps[(wr + g)     * FSP + j * 8 + 2 * t]     = f2tf(s[j][0]);
            Ps[(wr + g)     * FSP + j * 8 + 2 * t + 1] = f2tf(s[j][1]);
            Ps[(wr + g + 8) * FSP + j * 8 + 2 * t]     = f2tf(s[j][2]);
            Ps[(wr + g + 8) * FSP + j * 8 + 2 * t + 1] = f2tf(s[j][3]);
        }
        __syncwarp();

        // ---- O += P . V  (warp: 16 x 128) ----
        #pragma unroll
        for (int ks = 0; ks < 8; ks++) {
            unsigned pa[4];
            pa[0] = Ps[(wr + g)     * FSP + ks * 8 + t];
            pa[1] = Ps[(wr + g + 8) * FSP + ks * 8 + t];
            pa[2] = Ps[(wr + g)     * FSP + ks * 8 + t + 4];
            pa[3] = Ps[(wr + g + 8) * FSP + ks * 8 + t + 4];
            #pragma unroll
            for (int j = 0; j < 16; j++) {
                unsigned vb[2];
                vb[0] = Vs[(ks * 8 + t)     * FSV + j * 8 + g];
                vb[1] = Vs[(ks * 8 + t + 4) * FSV + j * 8 + g];
                mma8(oacc[j], pa, vb);
            }
        }
    }

    // ---- epilogue: Y[b, q, h*D + d] = O / l ----
    const float il0 = 1.f / lrow[0];
    const float il1 = 1.f / lrow[1];
    float* y0 = Y + (((size_t)(b * T_ + q0 + wr + g)) * H_ + h) * D_;
    float* y1 = y0 + (size_t)8 * H_ * D_;
    #pragma unroll
    for (int j = 0; j < 16; j++) {
        int col = j * 8 + 2 * t;
        *(float2*)(y0 + col) = make_float2(oacc[j][0] * il0, oacc[j][1] * il0);
        *(float2*)(y1 + col) = make_float2(oacc[j][2] * il1, oacc[j][3] * il1);
    }
}

// ---------------------------------------------------------------------------
extern "C" void kernel_launch(void* const* d_in, const int* in_sizes, int n_in,
                              void* d_out, int out_size)
{
    const float* x    = (const float*)d_in[0];
    const float* cosb = (const float*)d_in[1];
    const float* sinb = (const float*)d_in[2];
    const float* Wq   = (const float*)d_in[3];
    const float* Wk   = (const float*)d_in[4];
    const float* Wv   = (const float*)d_in[5];
    const float* Wo   = (const float*)d_in[6];
    float* out = (float*)d_out;

    float *qlin, *klin, *vlin, *qt, *ktp, *y;
    cudaGetSymbolAddress((void**)&qlin, g_qlin);
    cudaGetSymbolAddress((void**)&klin, g_klin);
    cudaGetSymbolAddress((void**)&vlin, g_vlin);
    cudaGetSymbolAddress((void**)&qt,   g_qt);
    cudaGetSymbolAddress((void**)&ktp,  g_kt);
    cudaGetSymbolAddress((void**)&y,    g_y);

    const int M = B_ * T_;  // 4096

    // QKV projections (tf32 tensor cores)
    gemm_tf32<<<dim3((H_ * D_) / 128, M / 128), 256>>>(x, Wq, qlin, M, H_ * D_, C_);
    gemm_tf32<<<dim3((KVH_ * D_) / 128, M / 128), 256>>>(x, Wk, klin, M, KVH_ * D_, C_);
    gemm_tf32<<<dim3((KVH_ * D_) / 128, M / 128), 256>>>(x, Wv, vlin, M, KVH_ * D_, C_);

    // RoPE + RMSNorm (+ fold softmax scale 1/sqrt(D) into q)
    rope_rms_kernel<<<B_ * T_ * H_, 64>>>(qlin, cosb, sinb, qt, H_,
                                          0.08838834764831845f);
    rope_rms_kernel<<<B_ * T_ * KVH_, 64>>>(klin, cosb, sinb, ktp, KVH_, 1.0f);

    // Flash attention (tf32 tensor cores)
    size_t smem = (size_t)(128 * FSQ + 64 * FSQ + 64 * FSV + 128 * FSP) * 4; // 171008 B
    cudaFuncSetAttribute(flash_tf32,
                         cudaFuncAttributeMaxDynamicSharedMemorySize, (int)smem);
    flash_tf32<<<dim3(T_ / 128, B_ * H_), 256, smem>>>(qt, ktp, vlin, y);

    // Output projection
    gemm_tf32<<<dim3(C_ / 128, M / 128), 256>>>(y, Wo, out, M, C_, C_);
}

// round 4
// speedup vs baseline: 4.1964x; 1.1660x over previous
#include <cuda_runtime.h>
#include <math.h>
#include <stdint.h>

#define B_    2
#define T_    2048
#define C_    2048
#define H_    16
#define KVH_  4
#define D_    128
#define GROUPS_ (H_/KVH_)
#define EPS_  1.1920929e-07f

#define GK    2048          // K dim of all big GEMMs
#define NIT   64            // GK / 32

// ---------------- scratch (device globals; no cudaMalloc allowed) ----------
__device__ float g_qt  [B_*T_*H_*D_];     // [B, H, T, D]  rope+rms+scale
__device__ float g_kt  [B_*T_*KVH_*D_];   // [B, KVH, T, D] rope+rms
__device__ float g_vlin[B_*T_*KVH_*D_];   // [B*T, KVH*D]
__device__ float g_y   [B_*T_*H_*D_];     // [B, T, H*D]

// ---------------------------------------------------------------------------
// tf32 helpers
// ---------------------------------------------------------------------------
__device__ __forceinline__ unsigned f2tf(float f) {
    unsigned u;
    asm("cvt.rna.tf32.f32 %0, %1;" : "=r"(u) : "f"(f));
    return u;
}

__device__ __forceinline__ void mma8(float* d, const unsigned* a, const unsigned* b) {
    asm volatile(
        "mma.sync.aligned.m16n8k8.row.col.f32.tf32.tf32.f32 "
        "{%0,%1,%2,%3}, {%4,%5,%6,%7}, {%8,%9}, {%0,%1,%2,%3};\n"
        : "+f"(d[0]), "+f"(d[1]), "+f"(d[2]), "+f"(d[3])
        : "r"(a[0]), "r"(a[1]), "r"(a[2]), "r"(a[3]), "r"(b[0]), "r"(b[1]));
}

// ---------------------------------------------------------------------------
// Shared GEMM machinery: 128x128 CTA tile, BK=32, 256 thr = 8 warps (4M x 2N),
// warp tile 32x64, smem double-buffered (stride 36), reg-prefetch pipeline.
// ---------------------------------------------------------------------------
__device__ __forceinline__ void ldg_tile(const float* Ab, const float* Wb, int k0,
                                         int tid, float4* ra, float4* rw) {
    #pragma unroll
    for (int l = 0; l < 4; l++) {
        int idx = tid + l * 256;            // 0..1023
        int r  = idx >> 3;
        int c4 = (idx & 7) * 4;
        ra[l] = *(const float4*)(Ab + (size_t)r * GK + k0 + c4);
        rw[l] = *(const float4*)(Wb + (size_t)r * GK + k0 + c4);
    }
}

__device__ __forceinline__ void sts_tile(unsigned* As, unsigned* Ws, int tid,
                                         const float4* ra, const float4* rw) {
    #pragma unroll
    for (int l = 0; l < 4; l++) {
        int idx = tid + l * 256;
        int r  = idx >> 3;
        int c4 = (idx & 7) * 4;
        unsigned* pa = &As[r * 36 + c4];
        pa[0] = f2tf(ra[l].x); pa[1] = f2tf(ra[l].y);
        pa[2] = f2tf(ra[l].z); pa[3] = f2tf(ra[l].w);
        unsigned* pw = &Ws[r * 36 + c4];
        pw[0] = f2tf(rw[l].x); pw[1] = f2tf(rw[l].y);
        pw[2] = f2tf(rw[l].z); pw[3] = f2tf(rw[l].w);
    }
}

__device__ __forceinline__ void mma_tile(const unsigned* As, const unsigned* Ws,
                                         int wm, int wn, int g, int t,
                                         float acc[2][8][4]) {
    #pragma unroll
    for (int kk = 0; kk < 32; kk += 8) {
        unsigned a[2][4], b[8][2];
        #pragma unroll
        for (int mi = 0; mi < 2; mi++) {
            int r = wm + mi * 16;
            a[mi][0] = As[(r + g)     * 36 + kk + t];
            a[mi][1] = As[(r + g + 8) * 36 + kk + t];
            a[mi][2] = As[(r + g)     * 36 + kk + t + 4];
            a[mi][3] = As[(r + g + 8) * 36 + kk + t + 4];
        }
        #pragma unroll
        for (int j = 0; j < 8; j++) {
            b[j][0] = Ws[(wn + j * 8 + g) * 36 + kk + t];
            b[j][1] = Ws[(wn + j * 8 + g) * 36 + kk + t + 4];
        }
        #pragma unroll
        for (int mi = 0; mi < 2; mi++)
            #pragma unroll
            for (int j = 0; j < 8; j++)
                mma8(acc[mi][j], a[mi], b[j]);
    }
}

#define GEMM_MAINLOOP(Ab, Wb)                                                  \
    float acc[2][8][4];                                                        \
    _Pragma("unroll")                                                          \
    for (int mi = 0; mi < 2; mi++)                                             \
        _Pragma("unroll")                                                      \
        for (int j = 0; j < 8; j++)                                            \
            _Pragma("unroll")                                                  \
            for (int c = 0; c < 4; c++) acc[mi][j][c] = 0.f;                   \
    {                                                                          \
        float4 ra[4], rw[4];                                                   \
        ldg_tile(Ab, Wb, 0, tid, ra, rw);                                      \
        sts_tile(As0, Ws0, tid, ra, rw);                                       \
        __syncthreads();                                                       \
        for (int it = 0; it < NIT; it++) {                                     \
            unsigned* Ac = (it & 1) ? As1 : As0;                               \
            unsigned* Wc = (it & 1) ? Ws1 : Ws0;                               \
            unsigned* An = (it & 1) ? As0 : As1;                               \
            unsigned* Wn = (it & 1) ? Ws0 : Ws1;                               \
            if (it + 1 < NIT) ldg_tile(Ab, Wb, (it + 1) * 32, tid, ra, rw);    \
            mma_tile(Ac, Wc, wm, wn, g, t, acc);                               \
            if (it + 1 < NIT) sts_tile(An, Wn, tid, ra, rw);                   \
            __syncthreads();                                                   \
        }                                                                      \
    }

// smem: 4 buffers of 128*36 words = 73728 bytes total
#define GEMM_SMEM (4 * 128 * 36 * 4)

// ---------------------------------------------------------------------------
// Fused QKV projection + RoPE + RMSNorm epilogue.
// grid = (24, 32): nb<16 -> Q head nb; nb in [16,20) -> K head nb-16;
// nb in [20,24) -> V head nb-20 (plain write).
// ---------------------------------------------------------------------------
__global__ __launch_bounds__(256) void qkv_gemm(
    const float* __restrict__ x,
    const float* __restrict__ Wq, const float* __restrict__ Wk,
    const float* __restrict__ Wv,
    const float* __restrict__ cosb, const float* __restrict__ sinb,
    float* __restrict__ qt, float* __restrict__ kt, float* __restrict__ vlin)
{
    extern __shared__ unsigned sm[];
    unsigned* As0 = sm;
    unsigned* Ws0 = sm + 128 * 36;
    unsigned* As1 = sm + 2 * 128 * 36;
    unsigned* Ws1 = sm + 3 * 128 * 36;

    const int tid  = threadIdx.x;
    const int lane = tid & 31;
    const int wid  = tid >> 5;
    const int g    = lane >> 2;
    const int t    = lane & 3;
    const int wm = (wid & 3) * 32;
    const int wn = (wid >> 2) * 64;
    const int m0 = blockIdx.y * 128;
    const int nb = blockIdx.x;

    const float* W;
    int nrow;
    if (nb < 16)      { W = Wq; nrow = nb * 128; }
    else if (nb < 20) { W = Wk; nrow = (nb - 16) * 128; }
    else              { W = Wv; nrow = (nb - 20) * 128; }
    const float* Ab = x + (size_t)m0 * GK;
    const float* Wb = W + (size_t)nrow * GK;

    GEMM_MAINLOOP(Ab, Wb)

    if (nb >= 20) {
        // ---- V: plain write to [B*T, KVH*D] ----
        const int n0 = (nb - 20) * 128;
        #pragma unroll
        for (int mi = 0; mi < 2; mi++) {
            int r0 = m0 + wm + mi * 16 + g;
            #pragma unroll
            for (int j = 0; j < 8; j++) {
                int cc = n0 + wn + j * 8 + 2 * t;
                *(float2*)(vlin + (size_t)r0 * (KVH_ * D_) + cc) =
                    make_float2(acc[mi][j][0], acc[mi][j][1]);
                *(float2*)(vlin + (size_t)(r0 + 8) * (KVH_ * D_) + cc) =
                    make_float2(acc[mi][j][2], acc[mi][j][3]);
            }
        }
        return;
    }

    // ---- Q/K: stage acc -> smem, then rope + rmsnorm + transpose ----
    float* St = (float*)sm;   // 128 rows x stride 132 floats = 67584 B <= 73728
    #pragma unroll
    for (int mi = 0; mi < 2; mi++) {
        int r0 = wm + mi * 16 + g;
        #pragma unroll
        for (int j = 0; j < 8; j++) {
            int cc = wn + j * 8 + 2 * t;
            St[r0 * 132 + cc]           = acc[mi][j][0];
            St[r0 * 132 + cc + 1]       = acc[mi][j][1];
            St[(r0 + 8) * 132 + cc]     = acc[mi][j][2];
            St[(r0 + 8) * 132 + cc + 1] = acc[mi][j][3];
        }
    }
    __syncthreads();

    {
        const int r  = tid >> 1;        // row 0..127
        const int hf = tid & 1;         // half of the 64 rope pairs
        const int m  = m0 + r;
        const int bb = m >> 11;         // m / T_
        const int tt = m & (T_ - 1);
        const float scale = (nb < 16) ? 0.08838834764831845f : 1.0f;

        const float* cr = cosb + tt * 64 + hf * 32;
        const float* sr = sinb + tt * 64 + hf * 32;
        const float* x1p = St + r * 132 + hf * 32;
        const float* x2p = x1p + 64;

        float o1[32], o2[32];
        float ss = 0.f;
        #pragma unroll
        for (int jj = 0; jj < 32; jj += 4) {
            float4 x1 = *(const float4*)(x1p + jj);
            float4 x2 = *(const float4*)(x2p + jj);
            float4 cv = *(const float4*)(cr + jj);
            float4 sv = *(const float4*)(sr + jj);
            float a0 = x1.x * cv.x + x2.x * sv.x, b0 = x2.x * cv.x - x1.x * sv.x;
            float a1 = x1.y * cv.y + x2.y * sv.y, b1 = x2.y * cv.y - x1.y * sv.y;
            float a2 = x1.z * cv.z + x2.z * sv.z, b2 = x2.z * cv.z - x1.z * sv.z;
            float a3 = x1.w * cv.w + x2.w * sv.w, b3 = x2.w * cv.w - x1.w * sv.w;
            o1[jj] = a0; o1[jj+1] = a1; o1[jj+2] = a2; o1[jj+3] = a3;
            o2[jj] = b0; o2[jj+1] = b1; o2[jj+2] = b2; o2[jj+3] = b3;
            ss += a0*a0 + b0*b0 + a1*a1 + b1*b1 + a2*a2 + b2*b2 + a3*a3 + b3*b3;
        }
        ss += __shfl_xor_sync(0xffffffffu, ss, 1);
        const float rr = rsqrtf(ss * (1.f / 128.f) + EPS_) * scale;

        float* ob;
        if (nb < 16)
            ob = qt + (((size_t)(bb * H_ + nb) * T_ + tt) * D_);
        else
            ob = kt + (((size_t)(bb * KVH_ + (nb - 16)) * T_ + tt) * D_);

        #pragma unroll
        for (int jj = 0; jj < 32; jj += 4) {
            *(float4*)(ob + hf * 32 + jj) = make_float4(
                o1[jj] * rr, o1[jj+1] * rr, o1[jj+2] * rr, o1[jj+3] * rr);
            *(float4*)(ob + 64 + hf * 32 + jj) = make_float4(
                o2[jj] * rr, o2[jj+1] * rr, o2[jj+2] * rr, o2[jj+3] * rr);
        }
    }
}

// ---------------------------------------------------------------------------
// Plain GEMM (output projection):  C[m][n] = sum_k A[m][k] * W[n][k]
// ---------------------------------------------------------------------------
__global__ __launch_bounds__(256) void out_gemm(
    const float* __restrict__ A, const float* __restrict__ W,
    float* __restrict__ C, int N)
{
    extern __shared__ unsigned sm[];
    unsigned* As0 = sm;
    unsigned* Ws0 = sm + 128 * 36;
    unsigned* As1 = sm + 2 * 128 * 36;
    unsigned* Ws1 = sm + 3 * 128 * 36;

    const int tid  = threadIdx.x;
    const int lane = tid & 31;
    const int wid  = tid >> 5;
    const int g    = lane >> 2;
    const int t    = lane & 3;
    const int wm = (wid & 3) * 32;
    const int wn = (wid >> 2) * 64;
    const int m0 = blockIdx.y * 128;
    const int n0 = blockIdx.x * 128;

    const float* Ab = A + (size_t)m0 * GK;
    const float* Wb = W + (size_t)n0 * GK;

    GEMM_MAINLOOP(Ab, Wb)

    #pragma unroll
    for (int mi = 0; mi < 2; mi++) {
        int r0 = m0 + wm + mi * 16 + g;
        #pragma unroll
        for (int j = 0; j < 8; j++) {
            int cc = n0 + wn + j * 8 + 2 * t;
            *(float2*)(C + (size_t)r0 * N + cc) =
                make_float2(acc[mi][j][0], acc[mi][j][1]);
            *(float2*)(C + (size_t)(r0 + 8) * N + cc) =
                make_float2(acc[mi][j][2], acc[mi][j][3]);
        }
    }
}

// ---------------------------------------------------------------------------
// Causal flash attention, tf32 mma.sync, online softmax. (unchanged, proven)
// ---------------------------------------------------------------------------
#define FSQ 132
#define FSV 136
#define FSP 68

__global__ __launch_bounds__(256) void flash_tf32(
    const float* __restrict__ Qt, const float* __restrict__ Kt,
    const float* __restrict__ Vlin, float* __restrict__ Y)
{
    extern __shared__ unsigned smu[];
    unsigned* Qs = smu;
    unsigned* Ks = Qs + 128 * FSQ;
    unsigned* Vs = Ks + 64 * FSQ;
    unsigned* Ps = Vs + 64 * FSV;

    const int tid  = threadIdx.x;
    const int lane = tid & 31;
    const int wid  = tid >> 5;
    const int g    = lane >> 2;
    const int t    = lane & 3;
    const int qb = blockIdx.x;
    const int q0 = qb * 128;
    const int bh = blockIdx.y;
    const int b  = bh / H_;
    const int h  = bh % H_;
    const int kvh = h / GROUPS_;
    const int wr  = wid * 16;

    {
        const float* qbase = Qt + ((size_t)bh * T_ + q0) * D_;
        #pragma unroll
        for (int l = 0; l < 16; l++) {
            int idx = tid + l * 256;
            int r  = idx >> 5;
            int c4 = (idx & 31) * 4;
            float4 v = *(const float4*)(qbase + (size_t)r * D_ + c4);
            unsigned* p = &Qs[r * FSQ + c4];
            p[0] = f2tf(v.x); p[1] = f2tf(v.y); p[2] = f2tf(v.z); p[3] = f2tf(v.w);
        }
    }

    float oacc[16][4];
    #pragma unroll
    for (int j = 0; j < 16; j++)
        #pragma unroll
        for (int c = 0; c < 4; c++) oacc[j][c] = 0.f;
    float mrow[2] = {-INFINITY, -INFINITY};
    float lrow[2] = {0.f, 0.f};

    const float* kbase = Kt + ((size_t)(b * KVH_ + kvh) * T_) * D_;
    const float* vbase = Vlin + ((size_t)b * T_) * (KVH_ * D_) + kvh * D_;

    const int nkt = qb * 2 + 2;
    for (int kt = 0; kt < nkt; kt++) {
        const int k0 = kt * 64;
        __syncthreads();
        #pragma unroll
        for (int l = 0; l < 8; l++) {
            int idx = tid + l * 256;
            int r  = idx >> 5;
            int c4 = (idx & 31) * 4;
            float4 kv = *(const float4*)(kbase + (size_t)(k0 + r) * D_ + c4);
            unsigned* pk = &Ks[r * FSQ + c4];
            pk[0] = f2tf(kv.x); pk[1] = f2tf(kv.y); pk[2] = f2tf(kv.z); pk[3] = f2tf(kv.w);
            float4 vv = *(const float4*)(vbase + (size_t)(k0 + r) * (KVH_ * D_) + c4);
            unsigned* pv = &Vs[r * FSV + c4];
            pv[0] = f2tf(vv.x); pv[1] = f2tf(vv.y); pv[2] = f2tf(vv.z); pv[3] = f2tf(vv.w);
        }
        __syncthreads();

        float s[8][4];
        #pragma unroll
        for (int j = 0; j < 8; j++)
            #pragma unroll
            for (int c = 0; c < 4; c++) s[j][c] = 0.f;

        #pragma unroll
        for (int ks = 0; ks < 16; ks++) {
            unsigned qa[4];
            qa[0] = Qs[(wr + g)     * FSQ + ks * 8 + t];
            qa[1] = Qs[(wr + g + 8) * FSQ + ks * 8 + t];
            qa[2] = Qs[(wr + g)     * FSQ + ks * 8 + t + 4];
            qa[3] = Qs[(wr + g + 8) * FSQ + ks * 8 + t + 4];
            #pragma unroll
            for (int j = 0; j < 8; j++) {
                unsigned kb[2];
                kb[0] = Ks[(j * 8 + g) * FSQ + ks * 8 + t];
                kb[1] = Ks[(j * 8 + g) * FSQ + ks * 8 + t + 4];
                mma8(s[j], qa, kb);
            }
        }

        if (kt >= nkt - 2) {
            int row0 = q0 + wr + g;
            int row1 = row0 + 8;
            #pragma unroll
            for (int j = 0; j < 8; j++) {
                int c0 = k0 + j * 8 + 2 * t;
                int c1 = c0 + 1;
                if (c0 > row0) s[j][0] = -1e30f;
                if (c1 > row0) s[j][1] = -1e30f;
                if (c0 > row1) s[j][2] = -1e30f;
                if (c1 > row1) s[j][3] = -1e30f;
            }
        }

        #pragma unroll
        for (int ri = 0; ri < 2; ri++) {
            const int i0 = ri * 2, i1 = ri * 2 + 1;
            float mx = -1e30f;
            #pragma unroll
            for (int j = 0; j < 8; j++)
                mx = fmaxf(mx, fmaxf(s[j][i0], s[j][i1]));
            mx = fmaxf(mx, __shfl_xor_sync(0xffffffffu, mx, 1));
            mx = fmaxf(mx, __shfl_xor_sync(0xffffffffu, mx, 2));
            float mnew = fmaxf(mrow[ri], mx);
            float alpha = __expf(mrow[ri] - mnew);
            float rs = 0.f;
            #pragma unroll
            for (int j = 0; j < 8; j++) {
                float p0 = __expf(s[j][i0] - mnew);
                float p1 = __expf(s[j][i1] - mnew);
                s[j][i0] = p0; s[j][i1] = p1;
                rs += p0 + p1;
            }
            rs += __shfl_xor_sync(0xffffffffu, rs, 1);
            rs += __shfl_xor_sync(0xffffffffu, rs, 2);
            lrow[ri] = lrow[ri] * alpha + rs;
            mrow[ri] = mnew;
            #pragma unroll
            for (int j = 0; j < 16; j++) {
                oacc[j][i0] *= alpha;
                oacc[j][i1] *= alpha;
            }
        }

        #pragma unroll
        for (int j = 0; j < 8; j++) {
            Ps[(wr + g)     * FSP + j * 8 + 2 * t]     = f2tf(s[j][0]);
            Ps[(wr + g)     * FSP + j * 8 + 2 * t + 1] = f2tf(s[j][1]);
            Ps[(wr + g + 8) * FSP + j * 8 + 2 * t]     = f2tf(s[j][2]);
            Ps[(wr + g + 8) * FSP + j * 8 + 2 * t + 1] = f2tf(s[j][3]);
        }
        __syncwarp();

        #pragma unroll
        for (int ks = 0; ks < 8; ks++) {
            unsigned pa[4];
            pa[0] = Ps[(wr + g)     * FSP + ks * 8 + t];
            pa[1] = Ps[(wr + g + 8) * FSP + ks * 8 + t];
            pa[2] = Ps[(wr + g)     * FSP + ks * 8 + t + 4];
            pa[3] = Ps[(wr + g + 8) * FSP + ks * 8 + t + 4];
            #pragma unroll
            for (int j = 0; j < 16; j++) {
                unsigned vb[2];
                vb[0] = Vs[(ks * 8 + t)     * FSV + j * 8 + g];
                vb[1] = Vs[(ks * 8 + t + 4) * FSV + j * 8 + g];
                mma8(oacc[j], pa, vb);
            }
        }
    }

    const float il0 = 1.f / lrow[0];
    const float il1 = 1.f / lrow[1];
    float* y0 = Y + (((size_t)(b * T_ + q0 + wr + g)) * H_ + h) * D_;
    float* y1 = y0 + (size_t)8 * H_ * D_;
    #pragma unroll
    for (int j = 0; j < 16; j++) {
        int col = j * 8 + 2 * t;
        *(float2*)(y0 + col) = make_float2(oacc[j][0] * il0, oacc[j][1] * il0);
        *(float2*)(y1 + col) = make_float2(oacc[j][2] * il1, oacc[j][3] * il1);
    }
}

// ---------------------------------------------------------------------------
extern "C" void kernel_launch(void* const* d_in, const int* in_sizes, int n_in,
                              void* d_out, int out_size)
{
    const float* x    = (const float*)d_in[0];
    const float* cosb = (const float*)d_in[1];
    const float* sinb = (const float*)d_in[2];
    const float* Wq   = (const float*)d_in[3];
    const float* Wk   = (const float*)d_in[4];
    const float* Wv   = (const float*)d_in[5];
    const float* Wo   = (const float*)d_in[6];
    float* out = (float*)d_out;

    float *qt, *ktp, *vlin, *y;
    cudaGetSymbolAddress((void**)&qt,   g_qt);
    cudaGetSymbolAddress((void**)&ktp,  g_kt);
    cudaGetSymbolAddress((void**)&vlin, g_vlin);
    cudaGetSymbolAddress((void**)&y,    g_y);

    cudaFuncSetAttribute(qkv_gemm, cudaFuncAttributeMaxDynamicSharedMemorySize,
                         GEMM_SMEM);
    cudaFuncSetAttribute(out_gemm, cudaFuncAttributeMaxDynamicSharedMemorySize,
                         GEMM_SMEM);

    // Fused QKV projection + RoPE + RMSNorm + transpose
    qkv_gemm<<<dim3(24, 32), 256, GEMM_SMEM>>>(x, Wq, Wk, Wv, cosb, sinb,
                                               qt, ktp, vlin);

    // Flash attention (tf32 mma.sync)
    size_t fsmem = (size_t)(128 * FSQ + 64 * FSQ + 64 * FSV + 128 * FSP) * 4;
    cudaFuncSetAttribute(flash_tf32,
                         cudaFuncAttributeMaxDynamicSharedMemorySize, (int)fsmem);
    flash_tf32<<<dim3(T_ / 128, B_ * H_), 256, fsmem>>>(qt, ktp, vlin, y);

    // Output projection
    out_gemm<<<dim3(C_ / 128, 32), 256, GEMM_SMEM>>>(y, Wo, out, C_);
}